// round 4
// baseline (speedup 1.0000x reference)
#include <cuda_runtime.h>

// Problem constants
#define FE_    1024
#define FE4_   256            // FE in float4
#define T_     2048
#define B_     4
#define NCH_   64             // chunks over T for the x-sum
#define TPC_   (T_ / NCH_)    // 32 timesteps per chunk
#define EPS_   1e-5f

// Scratch (device globals — allocation is forbidden). float4 for alignment.
__device__ float4 g_ccraw4[2 * FE4_];           // raw Wc@c per branch
__device__ float4 g_cc4[2 * FE4_];              // LayerNormed cond vectors
__device__ float4 g_part4[B_ * NCH_ * FE4_];    // partial sums of x over T
__device__ float4 g_sum4[B_ * FE4_];            // Σ_t x  (pre-modulation)
__device__ float4 g_p4[2 * B_ * FE4_];          // mv0 raw K-half partials [b][half][row]
__device__ float4 g_q4[2 * B_ * FE4_];          // mv1 raw K-half partials [b][half][row]

// ---------------------------------------------------------------------------
// K1 (fused): blocks [0,256): partial x-sum over T.
//             blocks [256,320): cond GEMV  ccraw = Wc @ c_flat  (v & o).
// ---------------------------------------------------------------------------
__global__ void k1_fused(const float4* __restrict__ x4,
                         const float*  __restrict__ c,
                         const float4* __restrict__ vWc4,
                         const float4* __restrict__ oWc4)
{
    const int bid = blockIdx.x;
    const int tid = threadIdx.x;          // 0..255

    if (bid < B_ * NCH_) {
        // ---- x partial sum: one float4 lane per thread, TPC_ timesteps ----
        const int b  = bid >> 6;          // / NCH_
        const int ch = bid & 63;          // % NCH_
        const float4* p = x4 + (size_t)b * (T_ * FE4_)
                             + (size_t)ch * (TPC_ * FE4_) + tid;
        float4 a0 = make_float4(0.f, 0.f, 0.f, 0.f);
        float4 a1 = make_float4(0.f, 0.f, 0.f, 0.f);
        #pragma unroll 8
        for (int t = 0; t < TPC_; t += 2) {
            float4 u = p[(size_t)t * FE4_];
            float4 v = p[(size_t)(t + 1) * FE4_];
            a0.x += u.x; a0.y += u.y; a0.z += u.z; a0.w += u.w;
            a1.x += v.x; a1.y += v.y; a1.z += v.z; a1.w += v.w;
        }
        g_part4[(size_t)bid * FE4_ + tid] =
            make_float4(a0.x + a1.x, a0.y + a1.y, a0.z + a1.z, a0.w + a1.w);
    } else {
        // ---- cond GEMV: 64 blocks, 32 rows each; warp handles 4 rows ----
        const int idx    = bid - B_ * NCH_;   // 0..63
        const int branch = idx >> 5;          // 0=v, 1=o
        const int rblk   = idx & 31;          // 32 row-tiles of 32 rows
        const float4* Wc4 = (branch == 0) ? vWc4 : oWc4;

        __shared__ float4 s_c4[64];           // c_flat: 256 floats
        if (tid < 64) s_c4[tid] = reinterpret_cast<const float4*>(c)[tid];
        __syncthreads();

        const int lane = tid & 31;
        const int warp = tid >> 5;            // 0..7
        float* outp = reinterpret_cast<float*>(g_ccraw4) + branch * FE_;

        #pragma unroll
        for (int rr = 0; rr < 4; rr++) {
            const int row = rblk * 32 + warp * 4 + rr;
            const float4* wr = Wc4 + (size_t)row * 64;   // 256 floats = 64 f4
            float4 w0 = wr[lane], w1 = wr[lane + 32];
            float4 c0 = s_c4[lane], c1 = s_c4[lane + 32];
            float acc = w0.x*c0.x + w0.y*c0.y + w0.z*c0.z + w0.w*c0.w
                      + w1.x*c1.x + w1.y*c1.y + w1.z*c1.z + w1.w*c1.w;
            #pragma unroll
            for (int off = 16; off; off >>= 1)
                acc += __shfl_down_sync(0xffffffffu, acc, off);
            if (lane == 0) outp[row] = acc;
        }
    }
}

// ---------------------------------------------------------------------------
// K2 (tiny): blocks 0,1: LayerNorm of ccraw -> g_cc (two-pass, deterministic).
//            blocks 2..5: reduce g_part -> g_sum for batch (bid-2).
// ---------------------------------------------------------------------------
__global__ void k2_small(const float* __restrict__ vg, const float* __restrict__ vb,
                         const float* __restrict__ og, const float* __restrict__ ob)
{
    const int bid = blockIdx.x;
    const int tid = threadIdx.x;          // 0..255

    if (bid < 2) {
        const float* raw = reinterpret_cast<const float*>(g_ccraw4) + bid * FE_;
        const float* gg  = (bid == 0) ? vg : og;
        const float* bb  = (bid == 0) ? vb : ob;
        float* outp = reinterpret_cast<float*>(g_cc4) + bid * FE_;

        __shared__ float s_red[256];
        float v0 = raw[tid], v1 = raw[tid + 256], v2 = raw[tid + 512], v3 = raw[tid + 768];

        s_red[tid] = v0 + v1 + v2 + v3;
        __syncthreads();
        for (int off = 128; off; off >>= 1) {
            if (tid < off) s_red[tid] += s_red[tid + off];
            __syncthreads();
        }
        const float mu = s_red[0] * (1.0f / FE_);
        __syncthreads();

        float d0 = v0 - mu, d1 = v1 - mu, d2 = v2 - mu, d3 = v3 - mu;
        s_red[tid] = d0*d0 + d1*d1 + d2*d2 + d3*d3;
        __syncthreads();
        for (int off = 128; off; off >>= 1) {
            if (tid < off) s_red[tid] += s_red[tid + off];
            __syncthreads();
        }
        const float rstd = rsqrtf(s_red[0] * (1.0f / FE_) + EPS_);

        outp[tid      ] = d0 * rstd * gg[tid      ] + bb[tid      ];
        outp[tid + 256] = d1 * rstd * gg[tid + 256] + bb[tid + 256];
        outp[tid + 512] = d2 * rstd * gg[tid + 512] + bb[tid + 512];
        outp[tid + 768] = d3 * rstd * gg[tid + 768] + bb[tid + 768];
    } else {
        const int b = bid - 2;
        float4 s = make_float4(0.f, 0.f, 0.f, 0.f);
        #pragma unroll 8
        for (int ch = 0; ch < NCH_; ch++) {
            float4 u = g_part4[((size_t)b * NCH_ + ch) * FE4_ + tid];
            s.x += u.x; s.y += u.y; s.z += u.z; s.w += u.w;
        }
        g_sum4[b * FE4_ + tid] = s;
    }
}

// ---------------------------------------------------------------------------
// mv0: partial dot of (g_sum ⊙ cc_v) with v_Wl rows, split over K in halves.
// grid = 2048 (row = bid>>1, half = bid&1), block = 128. One W float4/thread.
// Raw partials -> g_p[b*2+half][row]. Bias/scale applied at consume time.
// ---------------------------------------------------------------------------
__global__ void mv0_kernel(const float4* __restrict__ W4)
{
    const int bid  = blockIdx.x;
    const int row  = bid >> 1;
    const int half = bid & 1;
    const int tid  = threadIdx.x;          // 0..127
    const int lane = tid & 31;
    const int warp = tid >> 5;             // 0..3
    const int j    = half * 128 + tid;     // f4 column index

    // front-batched independent loads: 1 W (DRAM) + 5 m-related (L2)
    float4 w  = W4[(size_t)row * FE4_ + j];
    float4 cv = g_cc4[j];                  // cc_v
    float4 s0 = g_sum4[j          ];
    float4 s1 = g_sum4[j + FE4_   ];
    float4 s2 = g_sum4[j + 2*FE4_ ];
    float4 s3 = g_sum4[j + 3*FE4_ ];

    float4 wc = make_float4(w.x*cv.x, w.y*cv.y, w.z*cv.z, w.w*cv.w);
    float a0 = wc.x*s0.x + wc.y*s0.y + wc.z*s0.z + wc.w*s0.w;
    float a1 = wc.x*s1.x + wc.y*s1.y + wc.z*s1.z + wc.w*s1.w;
    float a2 = wc.x*s2.x + wc.y*s2.y + wc.z*s2.z + wc.w*s2.w;
    float a3 = wc.x*s3.x + wc.y*s3.y + wc.z*s3.z + wc.w*s3.w;

    #pragma unroll
    for (int off = 16; off; off >>= 1) {
        a0 += __shfl_down_sync(0xffffffffu, a0, off);
        a1 += __shfl_down_sync(0xffffffffu, a1, off);
        a2 += __shfl_down_sync(0xffffffffu, a2, off);
        a3 += __shfl_down_sync(0xffffffffu, a3, off);
    }
    __shared__ float sred[4][4];
    if (lane == 0) { sred[warp][0]=a0; sred[warp][1]=a1; sred[warp][2]=a2; sred[warp][3]=a3; }
    __syncthreads();
    if (tid < 4) {
        float s = sred[0][tid] + sred[1][tid] + sred[2][tid] + sred[3][tid];
        reinterpret_cast<float*>(g_p4)[(tid * 2 + half) * FE_ + row] = s;
    }
}

// ---------------------------------------------------------------------------
// mv1: same shape for o_Wl. m2[b][j] = (p0+p1 + T·v_bl)·cc_o, built inline
// from mv0 partials. Raw partials -> g_q[b*2+half][row].
// ---------------------------------------------------------------------------
__global__ void mv1_kernel(const float4* __restrict__ W4,
                           const float4* __restrict__ vbl4)
{
    const int bid  = blockIdx.x;
    const int row  = bid >> 1;
    const int half = bid & 1;
    const int tid  = threadIdx.x;          // 0..127
    const int lane = tid & 31;
    const int warp = tid >> 5;
    const int j    = half * 128 + tid;

    // front-batched: 1 W (DRAM) + 11 L2 loads, all independent
    float4 w   = W4[(size_t)row * FE4_ + j];
    float4 cco = g_cc4[FE4_ + j];
    float4 bl  = vbl4[j];
    float4 pa0 = g_p4[0*FE4_ + j], pb0 = g_p4[1*FE4_ + j];
    float4 pa1 = g_p4[2*FE4_ + j], pb1 = g_p4[3*FE4_ + j];
    float4 pa2 = g_p4[4*FE4_ + j], pb2 = g_p4[5*FE4_ + j];
    float4 pa3 = g_p4[6*FE4_ + j], pb3 = g_p4[7*FE4_ + j];

    const float Tf = (float)T_;
    float4 tb = make_float4(Tf*bl.x, Tf*bl.y, Tf*bl.z, Tf*bl.w);
    float4 m0 = make_float4((pa0.x+pb0.x+tb.x)*cco.x, (pa0.y+pb0.y+tb.y)*cco.y,
                            (pa0.z+pb0.z+tb.z)*cco.z, (pa0.w+pb0.w+tb.w)*cco.w);
    float4 m1 = make_float4((pa1.x+pb1.x+tb.x)*cco.x, (pa1.y+pb1.y+tb.y)*cco.y,
                            (pa1.z+pb1.z+tb.z)*cco.z, (pa1.w+pb1.w+tb.w)*cco.w);
    float4 m2 = make_float4((pa2.x+pb2.x+tb.x)*cco.x, (pa2.y+pb2.y+tb.y)*cco.y,
                            (pa2.z+pb2.z+tb.z)*cco.z, (pa2.w+pb2.w+tb.w)*cco.w);
    float4 m3 = make_float4((pa3.x+pb3.x+tb.x)*cco.x, (pa3.y+pb3.y+tb.y)*cco.y,
                            (pa3.z+pb3.z+tb.z)*cco.z, (pa3.w+pb3.w+tb.w)*cco.w);

    float a0 = w.x*m0.x + w.y*m0.y + w.z*m0.z + w.w*m0.w;
    float a1 = w.x*m1.x + w.y*m1.y + w.z*m1.z + w.w*m1.w;
    float a2 = w.x*m2.x + w.y*m2.y + w.z*m2.z + w.w*m2.w;
    float a3 = w.x*m3.x + w.y*m3.y + w.z*m3.z + w.w*m3.w;

    #pragma unroll
    for (int off = 16; off; off >>= 1) {
        a0 += __shfl_down_sync(0xffffffffu, a0, off);
        a1 += __shfl_down_sync(0xffffffffu, a1, off);
        a2 += __shfl_down_sync(0xffffffffu, a2, off);
        a3 += __shfl_down_sync(0xffffffffu, a3, off);
    }
    __shared__ float sred[4][4];
    if (lane == 0) { sred[warp][0]=a0; sred[warp][1]=a1; sred[warp][2]=a2; sred[warp][3]=a3; }
    __syncthreads();
    if (tid < 4) {
        float s = sred[0][tid] + sred[1][tid] + sred[2][tid] + sred[3][tid];
        reinterpret_cast<float*>(g_q4)[(tid * 2 + half) * FE_ + row] = s;
    }
}

// ---------------------------------------------------------------------------
// K5: broadcast z[b] = q0+q1+o_bl over T. Block: one batch row, 16 timesteps.
// ---------------------------------------------------------------------------
__global__ void bcast_kernel(float4* __restrict__ out4,
                             const float4* __restrict__ obl4)
{
    const int bid = blockIdx.x;            // 0..511
    const int tid = threadIdx.x;           // 0..255
    const int b   = bid >> 7;              // /128
    const int tg  = bid & 127;
    float4 q0 = g_q4[(b * 2    ) * FE4_ + tid];
    float4 q1 = g_q4[(b * 2 + 1) * FE4_ + tid];
    float4 bl = obl4[tid];
    const float4 zv = make_float4(q0.x + q1.x + bl.x, q0.y + q1.y + bl.y,
                                  q0.z + q1.z + bl.z, q0.w + q1.w + bl.w);
    float4* p = out4 + (size_t)b * (T_ * FE4_) + (size_t)tg * (16 * FE4_) + tid;
    #pragma unroll
    for (int t = 0; t < 16; t++)
        p[(size_t)t * FE4_] = zv;
}

// ---------------------------------------------------------------------------
extern "C" void kernel_launch(void* const* d_in, const int* in_sizes, int n_in,
                              void* d_out, int out_size)
{
    const float* x   = (const float*)d_in[0];
    const float* c   = (const float*)d_in[1];
    // q (3-7), k (8-12) branches and C (2) cancel analytically:
    //   y[b,t] = Σ_u v[b,u]  because Σ_q softmax(...) == 1 and the final
    //   einsum 'bftq,bufe->btfe' sums both q and u independently.
    const float* vWl = (const float*)d_in[13];
    const float* vbl = (const float*)d_in[14];
    const float* vWc = (const float*)d_in[15];
    const float* vg  = (const float*)d_in[16];
    const float* vb  = (const float*)d_in[17];
    const float* oWl = (const float*)d_in[18];
    const float* obl = (const float*)d_in[19];
    const float* oWc = (const float*)d_in[20];
    const float* og  = (const float*)d_in[21];
    const float* ob  = (const float*)d_in[22];

    k1_fused<<<B_ * NCH_ + 64, 256>>>((const float4*)x, c,
                                      (const float4*)vWc, (const float4*)oWc);
    k2_small<<<6, 256>>>(vg, vb, og, ob);
    mv0_kernel<<<FE_ * 2, 128>>>((const float4*)vWl);
    mv1_kernel<<<FE_ * 2, 128>>>((const float4*)oWl, (const float4*)vbl);
    bcast_kernel<<<B_ * T_ / 16, 256>>>((float4*)d_out, (const float4*)obl);
}

// round 5
// speedup vs baseline: 1.0697x; 1.0697x over previous
#include <cuda_runtime.h>

// Problem constants
#define FE_    1024
#define FE4_   256            // FE in float4
#define T_     2048
#define B_     4
#define G_     256            // grid size — MUST be <= guaranteed-resident capacity
#define NT_    256            // threads per block
#define NCH_   64             // chunks over T for the x-sum (B*NCH == G)
#define TPC_   (T_ / NCH_)    // 32 timesteps per chunk
#define EPS_   1e-5f

// Scratch (device globals — allocation is forbidden)
__device__ float4 g_part4[B_ * NCH_ * FE4_];   // x partial sums
__device__ float  g_ccraw[2 * FE_];            // raw Wc@c per branch
__device__ float2 g_lnpart[2 * 128];           // per-block (sum, sumsq) LN partials
__device__ float4 g_cc4[2 * FE4_];             // LayerNormed cond vectors (v, o)
__device__ float4 g_sum4[B_ * FE4_];           // sum_t x
__device__ float4 g_d04[B_ * FE4_];            // raw v-matvec dots
__device__ float4 g_z4[B_ * FE4_];             // final per-batch rows

// Grid barrier state (zero-initialized; count self-resets every use -> replay safe)
__device__ int g_bar_count[4];
__device__ int g_bar_gen[4];

__device__ __forceinline__ void grid_barrier(int i)
{
    __syncthreads();                       // block's writes ordered before t0's fence
    if (threadIdx.x == 0) {
        volatile int* genp = &g_bar_gen[i];
        __threadfence();                   // publish (cumulative w/ bar.sync)
        int my = *genp;                    // pre-arrival gen (release impossible yet)
        if (atomicAdd(&g_bar_count[i], 1) == G_ - 1) {
            g_bar_count[i] = 0;            // reset for next graph replay
            __threadfence();
            atomicExch(&g_bar_gen[i], my + 1);   // release
        } else {
            while (*genp == my) __nanosleep(64);
        }
        __threadfence();                   // acquire
    }
    __syncthreads();
}

__global__ void __launch_bounds__(NT_, 2)
mega_kernel(const float4* __restrict__ x4,
            const float4* __restrict__ c4,
            const float4* __restrict__ vWc4, const float4* __restrict__ oWc4,
            const float*  __restrict__ vg,   const float*  __restrict__ vb,
            const float*  __restrict__ og,   const float*  __restrict__ ob,
            const float4* __restrict__ vWl4, const float4* __restrict__ vbl4,
            const float4* __restrict__ oWl4, const float*  __restrict__ obl,
            float4* __restrict__ out4)
{
    __shared__ float4 sh_m4[B_ * FE4_];    // 16 KB staging (reused across phases)
    __shared__ float4 sh_c4[64];           // c_flat
    __shared__ float  sh_rv[8];
    __shared__ float  sh_red[8][4];

    const int bid  = blockIdx.x;
    const int tid  = threadIdx.x;
    const int lane = tid & 31;
    const int warp = tid >> 5;             // 0..7

    // ======================= Phase 1 =======================
    // 1a: x chunk sum (every block owns one (b, chunk) pair; B*NCH == G)
    if (tid < 64) sh_c4[tid] = c4[tid];
    {
        const int b  = bid >> 6;
        const int ch = bid & 63;
        const float4* p = x4 + (size_t)b * (T_ * FE4_)
                             + (size_t)ch * (TPC_ * FE4_) + tid;
        float4 a0 = make_float4(0.f, 0.f, 0.f, 0.f);
        float4 a1 = make_float4(0.f, 0.f, 0.f, 0.f);
        #pragma unroll 8
        for (int t = 0; t < TPC_; t += 2) {
            float4 u = p[(size_t)t * FE4_];
            float4 v = p[(size_t)(t + 1) * FE4_];
            a0.x += u.x; a0.y += u.y; a0.z += u.z; a0.w += u.w;
            a1.x += v.x; a1.y += v.y; a1.z += v.z; a1.w += v.w;
        }
        g_part4[(size_t)bid * FE4_ + tid] =
            make_float4(a0.x + a1.x, a0.y + a1.y, a0.z + a1.z, a0.w + a1.w);
    }
    __syncthreads();
    // 1b: cond GEMV — 128 blocks/branch, 8 rows each (warp per row)
    {
        const int branch = bid >> 7;
        const int rb     = bid & 127;
        const float4* Wc4 = branch ? oWc4 : vWc4;
        const int row = rb * 8 + warp;
        const float4* wr = Wc4 + (size_t)row * 64;    // 256 floats = 64 f4
        float4 w0 = wr[lane], w1 = wr[lane + 32];
        float4 c0 = sh_c4[lane], c1 = sh_c4[lane + 32];
        float acc = w0.x*c0.x + w0.y*c0.y + w0.z*c0.z + w0.w*c0.w
                  + w1.x*c1.x + w1.y*c1.y + w1.z*c1.z + w1.w*c1.w;
        #pragma unroll
        for (int off = 16; off; off >>= 1)
            acc += __shfl_down_sync(0xffffffffu, acc, off);
        if (lane == 0) { sh_rv[warp] = acc; g_ccraw[branch * FE_ + row] = acc; }
        __syncthreads();
        if (tid == 0) {
            float s = 0.f, q = 0.f;
            #pragma unroll
            for (int w = 0; w < 8; w++) { float v = sh_rv[w]; s += v; q += v * v; }
            g_lnpart[branch * 128 + rb] = make_float2(s, q);
        }
    }
    grid_barrier(0);

    // ======================= Phase 2 =======================
    if (bid < 2) {
        // LayerNorm finalize for branch `bid`
        float* red = reinterpret_cast<float*>(sh_m4);   // 512 floats
        float2 v = make_float2(0.f, 0.f);
        if (tid < 128) v = g_lnpart[bid * 128 + tid];
        red[tid] = v.x; red[256 + tid] = v.y;
        __syncthreads();
        for (int off = 128; off; off >>= 1) {
            if (tid < off) { red[tid] += red[tid + off]; red[256 + tid] += red[256 + tid + off]; }
            __syncthreads();
        }
        const float mu   = red[0] * (1.0f / FE_);
        const float var  = red[256] * (1.0f / FE_) - mu * mu;
        const float rstd = rsqrtf(var + EPS_);
        const float* gg  = bid ? og : vg;
        const float* bb  = bid ? ob : vb;
        const float* raw = g_ccraw + bid * FE_;
        float* cc = reinterpret_cast<float*>(g_cc4) + bid * FE_;
        #pragma unroll
        for (int k = 0; k < 4; k++) {
            const int j = tid + k * 256;
            cc[j] = (raw[j] - mu) * rstd * gg[j] + bb[j];
        }
    } else if (bid < 130) {
        // chunk reduce: 128 blocks, 8 f4 columns each (warp per column)
        const int idx = bid - 2;
        const int b   = idx >> 5;
        const int col = (idx & 31) * 8 + warp;
        float4 u = g_part4[(size_t)(b * NCH_ + lane     ) * FE4_ + col];
        float4 v = g_part4[(size_t)(b * NCH_ + lane + 32) * FE4_ + col];
        float4 a = make_float4(u.x + v.x, u.y + v.y, u.z + v.z, u.w + v.w);
        #pragma unroll
        for (int off = 16; off; off >>= 1) {
            a.x += __shfl_down_sync(0xffffffffu, a.x, off);
            a.y += __shfl_down_sync(0xffffffffu, a.y, off);
            a.z += __shfl_down_sync(0xffffffffu, a.z, off);
            a.w += __shfl_down_sync(0xffffffffu, a.w, off);
        }
        if (lane == 0) g_sum4[b * FE4_ + col] = a;
    }
    grid_barrier(1);

    // ======================= Phase 3: v-matvec =======================
    {
        float4 cv = g_cc4[tid];                       // cc_v
        #pragma unroll
        for (int b = 0; b < B_; b++) {
            float4 s = g_sum4[b * FE4_ + tid];
            sh_m4[b * FE4_ + tid] = make_float4(s.x*cv.x, s.y*cv.y, s.z*cv.z, s.w*cv.w);
        }
        __syncthreads();

        const int r0  = bid * 4;
        const int rw  = warp >> 1;                    // row within block
        const int hh  = warp & 1;                     // K half
        const float4* wr = vWl4 + (size_t)(r0 + rw) * FE4_ + hh * 128;
        float4 w0 = wr[lane], w1 = wr[lane + 32], w2 = wr[lane + 64], w3 = wr[lane + 96];
        float a0 = 0.f, a1 = 0.f, a2 = 0.f, a3 = 0.f;
        float4 wk[4] = {w0, w1, w2, w3};
        #pragma unroll
        for (int k = 0; k < 4; k++) {
            const int j = hh * 128 + lane + k * 32;
            float4 w = wk[k];
            float4 m0 = sh_m4[j], m1 = sh_m4[j + 256], m2 = sh_m4[j + 512], m3 = sh_m4[j + 768];
            a0 += w.x*m0.x + w.y*m0.y + w.z*m0.z + w.w*m0.w;
            a1 += w.x*m1.x + w.y*m1.y + w.z*m1.z + w.w*m1.w;
            a2 += w.x*m2.x + w.y*m2.y + w.z*m2.z + w.w*m2.w;
            a3 += w.x*m3.x + w.y*m3.y + w.z*m3.z + w.w*m3.w;
        }
        #pragma unroll
        for (int off = 16; off; off >>= 1) {
            a0 += __shfl_down_sync(0xffffffffu, a0, off);
            a1 += __shfl_down_sync(0xffffffffu, a1, off);
            a2 += __shfl_down_sync(0xffffffffu, a2, off);
            a3 += __shfl_down_sync(0xffffffffu, a3, off);
        }
        if (lane == 0) { sh_red[warp][0]=a0; sh_red[warp][1]=a1; sh_red[warp][2]=a2; sh_red[warp][3]=a3; }
        __syncthreads();
        if (tid < 16) {
            const int r = tid >> 2, b = tid & 3;
            const float val = sh_red[r * 2][b] + sh_red[r * 2 + 1][b];
            reinterpret_cast<float*>(g_d04)[b * FE_ + r0 + r] = val;
        }
    }
    grid_barrier(2);

    // ======================= Phase 4: o-matvec =======================
    {
        float4 cco = g_cc4[FE4_ + tid];               // cc_o
        float4 bl  = vbl4[tid];
        const float Tf = (float)T_;
        float4 tb = make_float4(Tf*bl.x, Tf*bl.y, Tf*bl.z, Tf*bl.w);
        #pragma unroll
        for (int b = 0; b < B_; b++) {
            float4 d = g_d04[b * FE4_ + tid];
            sh_m4[b * FE4_ + tid] = make_float4((d.x+tb.x)*cco.x, (d.y+tb.y)*cco.y,
                                                (d.z+tb.z)*cco.z, (d.w+tb.w)*cco.w);
        }
        __syncthreads();

        const int r0  = bid * 4;
        const int rw  = warp >> 1;
        const int hh  = warp & 1;
        const float4* wr = oWl4 + (size_t)(r0 + rw) * FE4_ + hh * 128;
        float4 w0 = wr[lane], w1 = wr[lane + 32], w2 = wr[lane + 64], w3 = wr[lane + 96];
        float a0 = 0.f, a1 = 0.f, a2 = 0.f, a3 = 0.f;
        float4 wk[4] = {w0, w1, w2, w3};
        #pragma unroll
        for (int k = 0; k < 4; k++) {
            const int j = hh * 128 + lane + k * 32;
            float4 w = wk[k];
            float4 m0 = sh_m4[j], m1 = sh_m4[j + 256], m2 = sh_m4[j + 512], m3 = sh_m4[j + 768];
            a0 += w.x*m0.x + w.y*m0.y + w.z*m0.z + w.w*m0.w;
            a1 += w.x*m1.x + w.y*m1.y + w.z*m1.z + w.w*m1.w;
            a2 += w.x*m2.x + w.y*m2.y + w.z*m2.z + w.w*m2.w;
            a3 += w.x*m3.x + w.y*m3.y + w.z*m3.z + w.w*m3.w;
        }
        #pragma unroll
        for (int off = 16; off; off >>= 1) {
            a0 += __shfl_down_sync(0xffffffffu, a0, off);
            a1 += __shfl_down_sync(0xffffffffu, a1, off);
            a2 += __shfl_down_sync(0xffffffffu, a2, off);
            a3 += __shfl_down_sync(0xffffffffu, a3, off);
        }
        if (lane == 0) { sh_red[warp][0]=a0; sh_red[warp][1]=a1; sh_red[warp][2]=a2; sh_red[warp][3]=a3; }
        __syncthreads();
        if (tid < 16) {
            const int r = tid >> 2, b = tid & 3;
            const float val = sh_red[r * 2][b] + sh_red[r * 2 + 1][b] + obl[r0 + r];
            reinterpret_cast<float*>(g_z4)[b * FE_ + r0 + r] = val;
        }
    }
    grid_barrier(3);

    // ======================= Phase 5: broadcast =======================
    {
        const int b  = bid >> 6;
        const int tg = bid & 63;                      // 32 timesteps per block
        const float4 zv = g_z4[b * FE4_ + tid];
        float4* p = out4 + (size_t)b * (T_ * FE4_) + (size_t)tg * (32 * FE4_) + tid;
        #pragma unroll
        for (int t = 0; t < 32; t++)
            p[(size_t)t * FE4_] = zv;
    }
}

// ---------------------------------------------------------------------------
extern "C" void kernel_launch(void* const* d_in, const int* in_sizes, int n_in,
                              void* d_out, int out_size)
{
    const float* x   = (const float*)d_in[0];
    const float* c   = (const float*)d_in[1];
    // q (3-7), k (8-12) branches and C (2) cancel analytically:
    //   y[b,t] = sum_u v[b,u]  because sum_q softmax(...) == 1 and the final
    //   einsum 'bftq,bufe->btfe' sums both q and u independently.
    const float* vWl = (const float*)d_in[13];
    const float* vbl = (const float*)d_in[14];
    const float* vWc = (const float*)d_in[15];
    const float* vg  = (const float*)d_in[16];
    const float* vb  = (const float*)d_in[17];
    const float* oWl = (const float*)d_in[18];
    const float* obl = (const float*)d_in[19];
    const float* oWc = (const float*)d_in[20];
    const float* og  = (const float*)d_in[21];
    const float* ob  = (const float*)d_in[22];

    mega_kernel<<<G_, NT_>>>((const float4*)x, (const float4*)c,
                             (const float4*)vWc, (const float4*)oWc,
                             vg, vb, og, ob,
                             (const float4*)vWl, (const float4*)vbl,
                             (const float4*)oWl, obl,
                             (float4*)d_out);
}

// round 6
// speedup vs baseline: 1.0982x; 1.0267x over previous
#include <cuda_runtime.h>

// Problem constants
#define FE_    1024
#define FE4_   256            // FE in float4
#define T_     2048
#define B_     4
#define G_     148            // one CTA per SM — perfect residency + balance
#define NT_    512
#define CPB_   37             // T-chunks per batch (4*37 == G_)
#define EPS_   1e-5f

// Scratch (device globals — allocation is forbidden)
__device__ float4 g_part4[G_ * FE4_];          // per-block x partial sums
__device__ float  g_ccraw[2 * FE_];            // raw Wc@c per branch
__device__ float4 g_cc4[2 * FE4_];             // LayerNormed cond vectors (v, o)
__device__ float4 g_sum4[B_ * FE4_];           // sum_t x
__device__ float4 g_d04[B_ * FE4_];            // raw v-matvec dots
__device__ float4 g_z4[B_ * FE4_];             // final per-batch rows

// Grid barrier state (zero-init; count self-resets each use -> replay safe)
__device__ int g_bar_count[4];
__device__ int g_bar_gen[4];

__device__ __forceinline__ void grid_barrier(int i)
{
    __syncthreads();
    if (threadIdx.x == 0) {
        volatile int* genp = &g_bar_gen[i];
        __threadfence();
        int my = *genp;
        if (atomicAdd(&g_bar_count[i], 1) == G_ - 1) {
            g_bar_count[i] = 0;
            __threadfence();
            atomicExch(&g_bar_gen[i], my + 1);
        } else {
            while (*genp == my) __nanosleep(32);
        }
        __threadfence();
    }
    __syncthreads();
}

__global__ void __launch_bounds__(NT_, 1)
mega_kernel(const float4* __restrict__ x4,
            const float4* __restrict__ c4,
            const float4* __restrict__ vWc4, const float4* __restrict__ oWc4,
            const float*  __restrict__ vg,   const float*  __restrict__ vb,
            const float*  __restrict__ og,   const float*  __restrict__ ob,
            const float4* __restrict__ vWl4, const float4* __restrict__ vbl4,
            const float4* __restrict__ oWl4, const float*  __restrict__ obl,
            float4* __restrict__ out4)
{
    __shared__ float4 sh_m4[4 * FE4_];     // 16 KB staging, reused per phase
    __shared__ float4 sh_c4[64];           // c_flat (256 floats)
    __shared__ float  sh_red[16][4];
    __shared__ float  sh_s[512];
    __shared__ float  sh_q[512];

    const int bid  = blockIdx.x;           // 0..147
    const int tid  = threadIdx.x;          // 0..511
    const int lane = tid & 31;
    const int warp = tid >> 5;             // 0..15

    const int b_own = bid / CPB_;          // batch this block owns for x/out
    const int cid   = bid % CPB_;
    const int t_lo  = (cid * T_) / CPB_;
    const int t_hi  = ((cid + 1) * T_) / CPB_;
    const int jcol  = tid & 255;           // f4 column
    const int hh    = tid >> 8;            // 0/1 sub-slot

    // ======================= Phase 1 =======================
    if (tid < 64) sh_c4[tid] = c4[tid];
    {   // x chunk sum: rows [t_lo, t_hi) of batch b_own, 2 rows in flight
        const float4* p = x4 + (size_t)b_own * (T_ * FE4_) + jcol;
        float4 a = make_float4(0.f, 0.f, 0.f, 0.f);
        #pragma unroll 4
        for (int t = t_lo + hh; t < t_hi; t += 2) {
            float4 u = p[(size_t)t * FE4_];
            a.x += u.x; a.y += u.y; a.z += u.z; a.w += u.w;
        }
        sh_m4[tid] = a;
    }
    __syncthreads();
    if (tid < 256) {
        float4 u = sh_m4[tid], v = sh_m4[tid + 256];
        g_part4[(size_t)bid * FE4_ + tid] =
            make_float4(u.x + v.x, u.y + v.y, u.z + v.z, u.w + v.w);
    }
    {   // cond GEMV: one row per warp, 2048 rows over 2368 warps
        const int gw = bid * 16 + warp;
        if (gw < 2 * FE_ / 1) {            // gw < 2048
            const int branch = gw >> 10;
            const int row    = gw & 1023;
            const float4* wr = (branch ? oWc4 : vWc4) + (size_t)row * 64;
            float4 w0 = wr[lane], w1 = wr[lane + 32];
            float4 c0 = sh_c4[lane], c1 = sh_c4[lane + 32];
            float acc = w0.x*c0.x + w0.y*c0.y + w0.z*c0.z + w0.w*c0.w
                      + w1.x*c1.x + w1.y*c1.y + w1.z*c1.z + w1.w*c1.w;
            #pragma unroll
            for (int off = 16; off; off >>= 1)
                acc += __shfl_down_sync(0xffffffffu, acc, off);
            if (lane == 0) g_ccraw[gw] = acc;
        }
    }
    grid_barrier(0);

    // ======================= Phase 2 =======================
    if (bid < 2) {
        // LayerNorm finalize for branch `bid` (1024 values, 512 threads)
        const float* raw = g_ccraw + bid * FE_;
        float v0 = raw[tid], v1 = raw[tid + 512];
        sh_s[tid] = v0 + v1;
        sh_q[tid] = v0 * v0 + v1 * v1;
        __syncthreads();
        for (int off = 256; off; off >>= 1) {
            if (tid < off) { sh_s[tid] += sh_s[tid + off]; sh_q[tid] += sh_q[tid + off]; }
            __syncthreads();
        }
        const float mu   = sh_s[0] * (1.0f / FE_);
        const float var  = sh_q[0] * (1.0f / FE_) - mu * mu;
        const float rstd = rsqrtf(var + EPS_);
        const float* gg  = bid ? og : vg;
        const float* bb  = bid ? ob : vb;
        float* cc = reinterpret_cast<float*>(g_cc4) + bid * FE_;
        cc[tid      ] = (v0 - mu) * rstd * gg[tid      ] + bb[tid      ];
        cc[tid + 512] = (v1 - mu) * rstd * gg[tid + 512] + bb[tid + 512];
    } else if (bid < 6) {
        // chunk reduce for batch (bid-2): 256 f4 columns, split c-range in 2
        const int b = bid - 2;
        const int c_lo = hh ? 19 : 0;
        const int c_hi = hh ? CPB_ : 19;
        float4 a = make_float4(0.f, 0.f, 0.f, 0.f);
        #pragma unroll 4
        for (int c = c_lo; c < c_hi; c++) {
            float4 u = g_part4[(size_t)(b * CPB_ + c) * FE4_ + jcol];
            a.x += u.x; a.y += u.y; a.z += u.z; a.w += u.w;
        }
        sh_m4[tid] = a;
        __syncthreads();
        if (tid < 256) {
            float4 u = sh_m4[tid], v = sh_m4[tid + 256];
            g_sum4[b * FE4_ + tid] =
                make_float4(u.x + v.x, u.y + v.y, u.z + v.z, u.w + v.w);
        }
    }
    grid_barrier(1);

    // ======================= Phase 3: v-matvec =======================
    {
        // stage m1[b][j] = sum[b][j] * cc_v[j]  (1024 f4, 2 per thread)
        #pragma unroll
        for (int k = 0; k < 2; k++) {
            const int idx = tid + k * 512;
            float4 s = g_sum4[idx], cv = g_cc4[idx & 255];
            sh_m4[idx] = make_float4(s.x*cv.x, s.y*cv.y, s.z*cv.z, s.w*cv.w);
        }
        __syncthreads();

        const int gw = bid * 16 + warp;      // warp slot
        if (gw < 2048) {
            const int row  = gw >> 1;
            const int half = gw & 1;
            const float4* wr = vWl4 + (size_t)row * FE4_ + half * 128;
            float4 w0 = wr[lane], w1 = wr[lane+32], w2 = wr[lane+64], w3 = wr[lane+96];
            float4 wk[4] = {w0, w1, w2, w3};
            float a0=0.f, a1=0.f, a2=0.f, a3=0.f;
            #pragma unroll
            for (int k = 0; k < 4; k++) {
                const int j = half * 128 + lane + k * 32;
                float4 w = wk[k];
                float4 m0 = sh_m4[j], m1 = sh_m4[j+256], m2 = sh_m4[j+512], m3 = sh_m4[j+768];
                a0 += w.x*m0.x + w.y*m0.y + w.z*m0.z + w.w*m0.w;
                a1 += w.x*m1.x + w.y*m1.y + w.z*m1.z + w.w*m1.w;
                a2 += w.x*m2.x + w.y*m2.y + w.z*m2.z + w.w*m2.w;
                a3 += w.x*m3.x + w.y*m3.y + w.z*m3.z + w.w*m3.w;
            }
            #pragma unroll
            for (int off = 16; off; off >>= 1) {
                a0 += __shfl_down_sync(0xffffffffu, a0, off);
                a1 += __shfl_down_sync(0xffffffffu, a1, off);
                a2 += __shfl_down_sync(0xffffffffu, a2, off);
                a3 += __shfl_down_sync(0xffffffffu, a3, off);
            }
            if (lane == 0) { sh_red[warp][0]=a0; sh_red[warp][1]=a1;
                             sh_red[warp][2]=a2; sh_red[warp][3]=a3; }
        }
        __syncthreads();
        if (bid < 128 && tid < 32) {
            const int r = tid >> 2, b = tid & 3;
            const float val = sh_red[2*r][b] + sh_red[2*r+1][b];
            reinterpret_cast<float*>(g_d04)[b * FE_ + bid * 8 + r] = val;
        }
    }
    grid_barrier(2);

    // ======================= Phase 4: o-matvec =======================
    {
        const float Tf = (float)T_;
        #pragma unroll
        for (int k = 0; k < 2; k++) {
            const int idx = tid + k * 512;
            const int j   = idx & 255;
            float4 d = g_d04[idx], cv = g_cc4[FE4_ + j], bl = vbl4[j];
            sh_m4[idx] = make_float4((d.x + Tf*bl.x)*cv.x, (d.y + Tf*bl.y)*cv.y,
                                     (d.z + Tf*bl.z)*cv.z, (d.w + Tf*bl.w)*cv.w);
        }
        __syncthreads();

        const int gw = bid * 16 + warp;
        if (gw < 2048) {
            const int row  = gw >> 1;
            const int half = gw & 1;
            const float4* wr = oWl4 + (size_t)row * FE4_ + half * 128;
            float4 w0 = wr[lane], w1 = wr[lane+32], w2 = wr[lane+64], w3 = wr[lane+96];
            float4 wk[4] = {w0, w1, w2, w3};
            float a0=0.f, a1=0.f, a2=0.f, a3=0.f;
            #pragma unroll
            for (int k = 0; k < 4; k++) {
                const int j = half * 128 + lane + k * 32;
                float4 w = wk[k];
                float4 m0 = sh_m4[j], m1 = sh_m4[j+256], m2 = sh_m4[j+512], m3 = sh_m4[j+768];
                a0 += w.x*m0.x + w.y*m0.y + w.z*m0.z + w.w*m0.w;
                a1 += w.x*m1.x + w.y*m1.y + w.z*m1.z + w.w*m1.w;
                a2 += w.x*m2.x + w.y*m2.y + w.z*m2.z + w.w*m2.w;
                a3 += w.x*m3.x + w.y*m3.y + w.z*m3.z + w.w*m3.w;
            }
            #pragma unroll
            for (int off = 16; off; off >>= 1) {
                a0 += __shfl_down_sync(0xffffffffu, a0, off);
                a1 += __shfl_down_sync(0xffffffffu, a1, off);
                a2 += __shfl_down_sync(0xffffffffu, a2, off);
                a3 += __shfl_down_sync(0xffffffffu, a3, off);
            }
            if (lane == 0) { sh_red[warp][0]=a0; sh_red[warp][1]=a1;
                             sh_red[warp][2]=a2; sh_red[warp][3]=a3; }
        }
        __syncthreads();
        if (bid < 128 && tid < 32) {
            const int r = tid >> 2, b = tid & 3;
            const int row = bid * 8 + r;
            const float val = sh_red[2*r][b] + sh_red[2*r+1][b] + obl[row];
            reinterpret_cast<float*>(g_z4)[b * FE_ + row] = val;
        }
    }
    grid_barrier(3);

    // ======================= Phase 5: broadcast =======================
    {
        const float4 zv = g_z4[b_own * FE4_ + jcol];
        float4* p = out4 + (size_t)b_own * (T_ * FE4_) + jcol;
        #pragma unroll 4
        for (int t = t_lo + hh; t < t_hi; t += 2)
            p[(size_t)t * FE4_] = zv;
    }
}

// ---------------------------------------------------------------------------
extern "C" void kernel_launch(void* const* d_in, const int* in_sizes, int n_in,
                              void* d_out, int out_size)
{
    const float* x   = (const float*)d_in[0];
    const float* c   = (const float*)d_in[1];
    // q (3-7), k (8-12) branches and C (2) cancel analytically:
    //   y[b,t] = sum_u v[b,u]  because sum_q softmax(...) == 1 and the final
    //   einsum 'bftq,bufe->btfe' sums both q and u independently.
    const float* vWl = (const float*)d_in[13];
    const float* vbl = (const float*)d_in[14];
    const float* vWc = (const float*)d_in[15];
    const float* vg  = (const float*)d_in[16];
    const float* vb  = (const float*)d_in[17];
    const float* oWl = (const float*)d_in[18];
    const float* obl = (const float*)d_in[19];
    const float* oWc = (const float*)d_in[20];
    const float* og  = (const float*)d_in[21];
    const float* ob  = (const float*)d_in[22];

    mega_kernel<<<G_, NT_>>>((const float4*)x, (const float4*)c,
                             (const float4*)vWc, (const float4*)oWc,
                             vg, vb, og, ob,
                             (const float4*)vWl, (const float4*)vbl,
                             (const float4*)oWl, obl,
                             (float4*)d_out);
}

// round 7
// speedup vs baseline: 1.2601x; 1.1474x over previous
#include <cuda_runtime.h>

// Problem constants
#define FE_    1024
#define FE4_   256            // FE in float4
#define T_     2048
#define B_     4
#define NCH_   32             // chunks over T for the x-sum
#define TPC_   (T_ / NCH_)    // 64 timesteps per chunk
#define GM_    128            // middle-kernel grid (all resident: 128 < 148 SMs)
#define EPS_   1e-5f

// Scratch (device globals — allocation is forbidden)
__device__ float4 g_part4[B_ * NCH_ * FE4_];   // x partial sums
__device__ float  g_ccraw[2 * FE_];            // raw Wc@c per branch
__device__ float4 g_cc4[2 * FE4_];             // LayerNormed cond vectors (v, o)
__device__ float4 g_sum4[B_ * FE4_];           // sum_t x
__device__ float4 g_d04[B_ * FE4_];            // raw v-matvec dots
__device__ float4 g_z4[B_ * FE4_];             // final per-batch rows

// Grid barrier state (zero-init; count self-resets each use -> replay safe)
__device__ int g_bar_count[2];
__device__ int g_bar_gen[2];

__device__ __forceinline__ void grid_barrier(int i)
{
    __syncthreads();
    if (threadIdx.x == 0) {
        volatile int* genp = &g_bar_gen[i];
        __threadfence();
        int my = *genp;
        if (atomicAdd(&g_bar_count[i], 1) == GM_ - 1) {
            g_bar_count[i] = 0;
            __threadfence();
            atomicExch(&g_bar_gen[i], my + 1);
        } else {
            while (*genp == my) __nanosleep(32);
        }
        __threadfence();
    }
    __syncthreads();
}

// ---------------------------------------------------------------------------
// K1 (fused): blocks [0,128): partial x-sum over T (constant trip count).
//             blocks [128,192): cond GEMV  ccraw = Wc @ c_flat  (v & o).
// ---------------------------------------------------------------------------
__global__ void k1_fused(const float4* __restrict__ x4,
                         const float*  __restrict__ c,
                         const float4* __restrict__ vWc4,
                         const float4* __restrict__ oWc4)
{
    const int bid = blockIdx.x;
    const int tid = threadIdx.x;          // 0..255

    if (bid < B_ * NCH_) {
        const int b  = bid >> 5;          // / NCH_
        const int ch = bid & 31;          // % NCH_
        const float4* p = x4 + (size_t)b * (T_ * FE4_)
                             + (size_t)ch * (TPC_ * FE4_) + tid;
        float4 a0 = make_float4(0.f, 0.f, 0.f, 0.f);
        float4 a1 = make_float4(0.f, 0.f, 0.f, 0.f);
        #pragma unroll 8
        for (int t = 0; t < TPC_; t += 2) {
            float4 u = p[(size_t)t * FE4_];
            float4 v = p[(size_t)(t + 1) * FE4_];
            a0.x += u.x; a0.y += u.y; a0.z += u.z; a0.w += u.w;
            a1.x += v.x; a1.y += v.y; a1.z += v.z; a1.w += v.w;
        }
        g_part4[(size_t)bid * FE4_ + tid] =
            make_float4(a0.x + a1.x, a0.y + a1.y, a0.z + a1.z, a0.w + a1.w);
    } else {
        const int idx    = bid - B_ * NCH_;   // 0..63
        const int branch = idx >> 5;          // 0=v, 1=o
        const int rblk   = idx & 31;
        const float4* Wc4 = (branch == 0) ? vWc4 : oWc4;

        __shared__ float4 s_c4[64];           // c_flat: 256 floats
        if (tid < 64) s_c4[tid] = reinterpret_cast<const float4*>(c)[tid];
        __syncthreads();

        const int lane = tid & 31;
        const int warp = tid >> 5;            // 0..7
        float* outp = g_ccraw + branch * FE_;

        #pragma unroll
        for (int rr = 0; rr < 4; rr++) {
            const int row = rblk * 32 + warp * 4 + rr;
            const float4* wr = Wc4 + (size_t)row * 64;
            float4 w0 = wr[lane], w1 = wr[lane + 32];
            float4 c0 = s_c4[lane], c1 = s_c4[lane + 32];
            float acc = w0.x*c0.x + w0.y*c0.y + w0.z*c0.z + w0.w*c0.w
                      + w1.x*c1.x + w1.y*c1.y + w1.z*c1.z + w1.w*c1.w;
            #pragma unroll
            for (int off = 16; off; off >>= 1)
                acc += __shfl_down_sync(0xffffffffu, acc, off);
            if (lane == 0) outp[row] = acc;
        }
    }
}

// ---------------------------------------------------------------------------
// K2 (middle, persistent over 128 blocks):
//   Phase A: chunk reduce -> g_sum;  blocks 0,1 also LayerNorm -> g_cc.
//   Phase B: v-matvec (8 rows/block, warp per row) -> g_d0.
//   Phase C: o-matvec -> g_z (bias folded in).
// ---------------------------------------------------------------------------
__global__ void __launch_bounds__(256, 1)
k2_middle(const float*  __restrict__ vg,   const float*  __restrict__ vb,
          const float*  __restrict__ og,   const float*  __restrict__ ob,
          const float4* __restrict__ vWl4, const float4* __restrict__ vbl4,
          const float4* __restrict__ oWl4, const float*  __restrict__ obl)
{
    __shared__ float4 sh_m4[B_ * FE4_];    // 16 KB staging
    __shared__ float  sh_s[256], sh_q[256];

    const int bid  = blockIdx.x;           // 0..127
    const int tid  = threadIdx.x;          // 0..255
    const int lane = tid & 31;
    const int warp = tid >> 5;              // 0..7

    // ---------- Phase A: chunk reduce (unit = (b, colgroup)) ----------
    {
        const int b   = bid >> 5;           // 0..3
        const int cg  = bid & 31;           // col group of 8
        const int col = cg * 8 + warp;
        // lane = chunk index (NCH_ == 32)
        float4 a = g_part4[(size_t)(b * NCH_ + lane) * FE4_ + col];
        #pragma unroll
        for (int off = 16; off; off >>= 1) {
            a.x += __shfl_down_sync(0xffffffffu, a.x, off);
            a.y += __shfl_down_sync(0xffffffffu, a.y, off);
            a.z += __shfl_down_sync(0xffffffffu, a.z, off);
            a.w += __shfl_down_sync(0xffffffffu, a.w, off);
        }
        if (lane == 0) g_sum4[b * FE4_ + col] = a;
    }
    if (bid < 2) {
        // LayerNorm finalize for branch `bid` (1024 values, 256 threads)
        const float* raw = g_ccraw + bid * FE_;
        float v0 = raw[tid], v1 = raw[tid + 256], v2 = raw[tid + 512], v3 = raw[tid + 768];
        sh_s[tid] = v0 + v1 + v2 + v3;
        sh_q[tid] = v0*v0 + v1*v1 + v2*v2 + v3*v3;
        __syncthreads();
        for (int off = 128; off; off >>= 1) {
            if (tid < off) { sh_s[tid] += sh_s[tid + off]; sh_q[tid] += sh_q[tid + off]; }
            __syncthreads();
        }
        const float mu   = sh_s[0] * (1.0f / FE_);
        const float var  = sh_q[0] * (1.0f / FE_) - mu * mu;
        const float rstd = rsqrtf(var + EPS_);
        const float* gg  = bid ? og : vg;
        const float* bb  = bid ? ob : vb;
        float* cc = reinterpret_cast<float*>(g_cc4) + bid * FE_;
        cc[tid      ] = (v0 - mu) * rstd * gg[tid      ] + bb[tid      ];
        cc[tid + 256] = (v1 - mu) * rstd * gg[tid + 256] + bb[tid + 256];
        cc[tid + 512] = (v2 - mu) * rstd * gg[tid + 512] + bb[tid + 512];
        cc[tid + 768] = (v3 - mu) * rstd * gg[tid + 768] + bb[tid + 768];
    }
    grid_barrier(0);

    // ---------- Phase B: v-matvec ----------
    {
        #pragma unroll
        for (int k = 0; k < 4; k++) {
            const int idx = tid + k * 256;
            float4 s = g_sum4[idx], cv = g_cc4[tid];
            sh_m4[idx] = make_float4(s.x*cv.x, s.y*cv.y, s.z*cv.z, s.w*cv.w);
        }
        __syncthreads();

        const int row = bid * 8 + warp;
        const float4* wr = vWl4 + (size_t)row * FE4_;
        float4 W0 = wr[lane      ], W1 = wr[lane +  32];
        float4 W2 = wr[lane +  64], W3 = wr[lane +  96];
        float4 W4 = wr[lane + 128], W5 = wr[lane + 160];
        float4 W6 = wr[lane + 192], W7 = wr[lane + 224];
        float4 Wk[8] = {W0, W1, W2, W3, W4, W5, W6, W7};
        float a0=0.f, a1=0.f, a2=0.f, a3=0.f;
        #pragma unroll
        for (int k = 0; k < 8; k++) {
            const int j = lane + k * 32;
            float4 w = Wk[k];
            float4 m0 = sh_m4[j], m1 = sh_m4[j+256], m2 = sh_m4[j+512], m3 = sh_m4[j+768];
            a0 += w.x*m0.x + w.y*m0.y + w.z*m0.z + w.w*m0.w;
            a1 += w.x*m1.x + w.y*m1.y + w.z*m1.z + w.w*m1.w;
            a2 += w.x*m2.x + w.y*m2.y + w.z*m2.z + w.w*m2.w;
            a3 += w.x*m3.x + w.y*m3.y + w.z*m3.z + w.w*m3.w;
        }
        #pragma unroll
        for (int off = 16; off; off >>= 1) {
            a0 += __shfl_down_sync(0xffffffffu, a0, off);
            a1 += __shfl_down_sync(0xffffffffu, a1, off);
            a2 += __shfl_down_sync(0xffffffffu, a2, off);
            a3 += __shfl_down_sync(0xffffffffu, a3, off);
        }
        if (lane == 0) {
            float* d0 = reinterpret_cast<float*>(g_d04);
            d0[0 * FE_ + row] = a0;
            d0[1 * FE_ + row] = a1;
            d0[2 * FE_ + row] = a2;
            d0[3 * FE_ + row] = a3;
        }
    }
    grid_barrier(1);

    // ---------- Phase C: o-matvec ----------
    {
        const float Tf = (float)T_;
        #pragma unroll
        for (int k = 0; k < 4; k++) {
            const int idx = tid + k * 256;
            float4 d = g_d04[idx], cv = g_cc4[FE4_ + tid], bl = vbl4[tid];
            sh_m4[idx] = make_float4((d.x + Tf*bl.x)*cv.x, (d.y + Tf*bl.y)*cv.y,
                                     (d.z + Tf*bl.z)*cv.z, (d.w + Tf*bl.w)*cv.w);
        }
        __syncthreads();

        const int row = bid * 8 + warp;
        const float4* wr = oWl4 + (size_t)row * FE4_;
        float4 W0 = wr[lane      ], W1 = wr[lane +  32];
        float4 W2 = wr[lane +  64], W3 = wr[lane +  96];
        float4 W4 = wr[lane + 128], W5 = wr[lane + 160];
        float4 W6 = wr[lane + 192], W7 = wr[lane + 224];
        float4 Wk[8] = {W0, W1, W2, W3, W4, W5, W6, W7};
        float a0=0.f, a1=0.f, a2=0.f, a3=0.f;
        #pragma unroll
        for (int k = 0; k < 8; k++) {
            const int j = lane + k * 32;
            float4 w = Wk[k];
            float4 m0 = sh_m4[j], m1 = sh_m4[j+256], m2 = sh_m4[j+512], m3 = sh_m4[j+768];
            a0 += w.x*m0.x + w.y*m0.y + w.z*m0.z + w.w*m0.w;
            a1 += w.x*m1.x + w.y*m1.y + w.z*m1.z + w.w*m1.w;
            a2 += w.x*m2.x + w.y*m2.y + w.z*m2.z + w.w*m2.w;
            a3 += w.x*m3.x + w.y*m3.y + w.z*m3.z + w.w*m3.w;
        }
        #pragma unroll
        for (int off = 16; off; off >>= 1) {
            a0 += __shfl_down_sync(0xffffffffu, a0, off);
            a1 += __shfl_down_sync(0xffffffffu, a1, off);
            a2 += __shfl_down_sync(0xffffffffu, a2, off);
            a3 += __shfl_down_sync(0xffffffffu, a3, off);
        }
        if (lane == 0) {
            const float bs = obl[row];
            float* z = reinterpret_cast<float*>(g_z4);
            z[0 * FE_ + row] = a0 + bs;
            z[1 * FE_ + row] = a1 + bs;
            z[2 * FE_ + row] = a2 + bs;
            z[3 * FE_ + row] = a3 + bs;
        }
    }
}

// ---------------------------------------------------------------------------
// K3: broadcast z[b] over T. Block: one batch row segment, 16 timesteps.
// ---------------------------------------------------------------------------
__global__ void bcast_kernel(float4* __restrict__ out4)
{
    const int bid = blockIdx.x;            // 0..511
    const int tid = threadIdx.x;           // 0..255
    const int b   = bid >> 7;
    const int tg  = bid & 127;
    const float4 zv = g_z4[b * FE4_ + tid];
    float4* p = out4 + (size_t)b * (T_ * FE4_) + (size_t)tg * (16 * FE4_) + tid;
    #pragma unroll
    for (int t = 0; t < 16; t++)
        p[(size_t)t * FE4_] = zv;
}

// ---------------------------------------------------------------------------
extern "C" void kernel_launch(void* const* d_in, const int* in_sizes, int n_in,
                              void* d_out, int out_size)
{
    const float* x   = (const float*)d_in[0];
    const float* c   = (const float*)d_in[1];
    // q (3-7), k (8-12) branches and C (2) cancel analytically:
    //   y[b,t] = sum_u v[b,u]  because sum_q softmax(...) == 1 and the final
    //   einsum 'bftq,bufe->btfe' sums both q and u independently.
    const float* vWl = (const float*)d_in[13];
    const float* vbl = (const float*)d_in[14];
    const float* vWc = (const float*)d_in[15];
    const float* vg  = (const float*)d_in[16];
    const float* vb  = (const float*)d_in[17];
    const float* oWl = (const float*)d_in[18];
    const float* obl = (const float*)d_in[19];
    const float* oWc = (const float*)d_in[20];
    const float* og  = (const float*)d_in[21];
    const float* ob  = (const float*)d_in[22];

    k1_fused<<<B_ * NCH_ + 64, 256>>>((const float4*)x, c,
                                      (const float4*)vWc, (const float4*)oWc);
    k2_middle<<<GM_, 256>>>(vg, vb, og, ob,
                            (const float4*)vWl, (const float4*)vbl,
                            (const float4*)oWl, obl);
    bcast_kernel<<<B_ * T_ / 16, 256>>>((float4*)d_out);
}